// round 4
// baseline (speedup 1.0000x reference)
#include <cuda_runtime.h>
#include <float.h>

// ---------------------------------------------------------------------------
// Problem shape
// ---------------------------------------------------------------------------
#define M_Q   2048
#define N_P   32768
#define D_F   256
#define D2    512

#define NPART 2
#define PART  (N_P / NPART)      // 16384 points per partition
#define TILE  2048               // candidates per SMEM tile
#define TP    (TILE / 2)         // packed units per tile (1024)
#define QPW   8                  // queries per warp

typedef unsigned long long ull;

// ---------------------------------------------------------------------------
// Device scratch
// ---------------------------------------------------------------------------
__device__ float2       g_nn_part[4][M_Q][NPART];  // (d2, idx-bits) partials
__device__ unsigned int g_xmax[D2];                // order-encoded channel max

// ---------------------------------------------------------------------------
// Packed f32x2 helpers (Blackwell)
// ---------------------------------------------------------------------------
__device__ __forceinline__ ull fma2(ull a, ull b, ull c) {
    ull d;
    asm("fma.rn.f32x2 %0, %1, %2, %3;" : "=l"(d) : "l"(a), "l"(b), "l"(c));
    return d;
}
__device__ __forceinline__ ull mul2(ull a, ull b) {
    ull d;
    asm("mul.rn.f32x2 %0, %1, %2;" : "=l"(d) : "l"(a), "l"(b));
    return d;
}
// fused: (lo,hi) = a*b + c, unpack folded into the same asm block so ptxas
// can alias the register pair instead of emitting MOVs.
__device__ __forceinline__ void fma2u(ull a, ull b, ull c, float& lo, float& hi) {
    asm("{\n\t.reg .b64 t;\n\t"
        "fma.rn.f32x2 t, %2, %3, %4;\n\t"
        "mov.b64 {%0, %1}, t;\n\t}"
        : "=f"(lo), "=f"(hi) : "l"(a), "l"(b), "l"(c));
}
__device__ __forceinline__ ull pack2(float lo, float hi) {
    ull r;
    asm("mov.b64 %0, {%1, %2};" : "=l"(r) : "f"(lo), "f"(hi));
    return r;
}

// Order-preserving float<->uint encode for atomicMax over mixed-sign floats.
__device__ __forceinline__ unsigned int enc_f(float f) {
    unsigned int u = __float_as_uint(f);
    return (u & 0x80000000u) ? ~u : (u | 0x80000000u);
}
__device__ __forceinline__ float dec_f(unsigned int u) {
    return __uint_as_float((u & 0x80000000u) ? (u & 0x7FFFFFFFu) : ~u);
}

// ---------------------------------------------------------------------------
// Kernel 1: brute-force NN, min-value main loop + deferred index rescan.
// d2' = |p|^2 - 2 q.p  (argmin-equivalent to |q-p|^2)
// Grid: 512 blocks = 64 qblocks x 4 searches x 2 partitions.
// Block: 128 thr = 4 warps, 8 queries/warp.
// ---------------------------------------------------------------------------
__global__ __launch_bounds__(128, 4)
void nn_kernel(const float* __restrict__ co, const float* __restrict__ cm,
               const float* __restrict__ p0, const float* __restrict__ p1,
               const float* __restrict__ p2, const float* __restrict__ p3)
{
    const int bx     = blockIdx.x;
    const int part   = bx & 1;
    const int search = (bx >> 1) & 3;
    const int qblk   = bx >> 3;               // 0..63
    const int tid    = threadIdx.x;
    const int warp   = tid >> 5;
    const int lane   = tid & 31;

    // init the gather-stage accumulator (stream order precedes gather kernel)
    if (bx < 4) g_xmax[bx * 128 + tid] = 0u;

    const float* __restrict__ q   = (search < 2) ? co : cm;
    const float* __restrict__ pos = (search == 0) ? p0 :
                                    (search == 1) ? p1 :
                                    (search == 2) ? p2 : p3;

    const int qbase = qblk * 32 + warp * QPW;

    ull   cx2[QPW], cy2[QPW], cz2[QPW];
    float best[QPW];
    int   btile[QPW];
#pragma unroll
    for (int j = 0; j < QPW; j++) {
        const int qi = qbase + j;
        const float nx = -2.0f * q[qi * 3 + 0];
        const float ny = -2.0f * q[qi * 3 + 1];
        const float nz = -2.0f * q[qi * 3 + 2];
        cx2[j] = pack2(nx, nx);
        cy2[j] = pack2(ny, ny);
        cz2[j] = pack2(nz, nz);
        best[j] = FLT_MAX;
        btile[j] = 0;
    }

    __shared__ ull sx[TP], sy[TP], sz[TP], sw[TP];   // 32 KB

    const int pbase = part * PART;

    for (int t0 = 0; t0 < PART; t0 += TILE) {
        __syncthreads();
        // cooperative tile load: pack pairs, precompute |p|^2 (packed order!)
        for (int u = tid; u < TP; u += 128) {
            const float2* pp =
                (const float2*)(pos + (size_t)(pbase + t0 + 2 * u) * 3);
            const float2 a = pp[0];            // x0 y0
            const float2 b = pp[1];            // z0 x1
            const float2 c = pp[2];            // y1 z1
            const ull x2 = pack2(a.x, b.y);
            const ull y2 = pack2(a.y, c.x);
            const ull z2 = pack2(b.x, c.y);
            ull w2 = mul2(z2, z2);
            w2 = fma2(y2, y2, w2);
            w2 = fma2(x2, x2, w2);
            sx[u] = x2; sy[u] = y2; sz[u] = z2; sw[u] = w2;
        }
        __syncthreads();

        float tmin[QPW];
#pragma unroll
        for (int j = 0; j < QPW; j++) tmin[j] = best[j];

#pragma unroll 2
        for (int k = lane; k < TP; k += 32) {
            const ull x2 = sx[k];
            const ull y2 = sy[k];
            const ull z2 = sz[k];
            const ull w2 = sw[k];
#pragma unroll
            for (int j = 0; j < QPW; j++) {
                ull t2 = fma2(x2, cx2[j], w2);
                t2 = fma2(y2, cy2[j], t2);
                float lo, hi;
                fma2u(z2, cz2[j], t2, lo, hi);
                tmin[j] = fminf(tmin[j], fminf(lo, hi));
            }
        }

        const int gb = pbase + t0;
#pragma unroll
        for (int j = 0; j < QPW; j++) {
            if (tmin[j] < best[j]) { best[j] = tmin[j]; btile[j] = gb; }
        }
    }

    // inter-lane lexicographic (best, btile) butterfly reduce
#pragma unroll
    for (int off = 16; off; off >>= 1) {
#pragma unroll
        for (int j = 0; j < QPW; j++) {
            const float ob = __shfl_xor_sync(0xffffffffu, best[j], off);
            const int   ot = __shfl_xor_sync(0xffffffffu, btile[j], off);
            if (ob < best[j] || (ob == best[j] && ot < btile[j])) {
                best[j] = ob; btile[j] = ot;
            }
        }
    }

    // deferred index rescan: one tile per query, recompute d2 bitwise-identically
    for (int j = 0; j < QPW; j++) {
        const float wb = best[j];      // warp-uniform
        const int   tb = btile[j];     // warp-uniform (global candidate base)
        int midx = 0x7fffffff;
#pragma unroll 2
        for (int k = lane; k < TP; k += 32) {
            const int i0 = tb + 2 * k;
            const float2* pp = (const float2*)(pos + (size_t)i0 * 3);
            const float2 a = pp[0];
            const float2 b = pp[1];
            const float2 c = pp[2];
            const ull x2 = pack2(a.x, b.y);
            const ull y2 = pack2(a.y, c.x);
            const ull z2 = pack2(b.x, c.y);
            ull w2 = mul2(z2, z2);
            w2 = fma2(y2, y2, w2);
            w2 = fma2(x2, x2, w2);
            ull t2 = fma2(x2, cx2[j], w2);
            t2 = fma2(y2, cy2[j], t2);
            float lo, hi;
            fma2u(z2, cz2[j], t2, lo, hi);
            if (lo == wb) midx = min(midx, i0);
            if (hi == wb) midx = min(midx, i0 + 1);
        }
#pragma unroll
        for (int off = 16; off; off >>= 1)
            midx = min(midx, __shfl_xor_sync(0xffffffffu, midx, off));

        if (lane == 0)
            g_nn_part[search][qbase + j][part] =
                make_float2(wb, __int_as_float(midx));
    }
}

// ---------------------------------------------------------------------------
// Kernel 2: reduce NN partials, gather feat rows, avg left/right, max-pool.
// Grid: 256 blocks = 2 sides x 128 chunks (16 rows each). 256 thr = channel.
// ---------------------------------------------------------------------------
__global__ __launch_bounds__(256)
void gather_max_kernel(const float* __restrict__ f0, const float* __restrict__ f1,
                       const float* __restrict__ f2, const float* __restrict__ f3)
{
    const int side  = blockIdx.x >> 7;     // 0 = orig, 1 = mut
    const int chunk = blockIdx.x & 127;
    const int c     = threadIdx.x;
    const int m0    = chunk * 16;

    __shared__ int sj[2][16];
    if (threadIdx.x < 32) {
        const int which = threadIdx.x >> 4;           // 0 = left, 1 = right
        const int m = m0 + (threadIdx.x & 15);
        const int s = side * 2 + which;
        float2 p = g_nn_part[s][m][0];
        float bd = p.x;
        int   bi = __float_as_int(p.y);
#pragma unroll
        for (int pt = 1; pt < NPART; pt++) {
            const float2 r = g_nn_part[s][m][pt];
            const int ri = __float_as_int(r.y);
            if (r.x < bd || (r.x == bd && ri < bi)) { bd = r.x; bi = ri; }
        }
        sj[which][threadIdx.x & 15] = bi;
    }
    __syncthreads();

    const float* __restrict__ fa = side ? f2 : f0;
    const float* __restrict__ fb = side ? f3 : f1;

    float mx = -FLT_MAX;
#pragma unroll
    for (int m = 0; m < 16; m++) {
        const float v = 0.5f * (fa[(size_t)sj[0][m] * D_F + c] +
                                fb[(size_t)sj[1][m] * D_F + c]);
        mx = fmaxf(mx, v);
    }
    atomicMax(&g_xmax[side * 256 + c], enc_f(mx));
}

// ---------------------------------------------------------------------------
// Kernel 3: decode x[512]; fc1 (relu) + fc2 fused. 1024 thr, 2 thr per row.
// ---------------------------------------------------------------------------
__global__ __launch_bounds__(1024)
void fc_kernel(const float* __restrict__ w1, const float* __restrict__ b1,
               const float* __restrict__ w2, const float* __restrict__ b2,
               float* __restrict__ out)
{
    __shared__ float xs[D2];
    __shared__ float hs[D2];
    const int t = threadIdx.x;

    if (t < D2) xs[t] = dec_f(g_xmax[t]);
    __syncthreads();

    const int j    = t >> 1;
    const int half = t & 1;
    const float4* __restrict__ wr4 =
        (const float4*)(w1 + (size_t)j * D2 + half * (D2 / 2));
    const float4* __restrict__ xs4 = (const float4*)(xs + half * (D2 / 2));
    float acc = 0.0f;
#pragma unroll 8
    for (int k = 0; k < D2 / 8; k++) {         // 64 float4 per half
        const float4 w = wr4[k];
        const float4 x = xs4[k];
        acc = fmaf(w.x, x.x, acc);
        acc = fmaf(w.y, x.y, acc);
        acc = fmaf(w.z, x.z, acc);
        acc = fmaf(w.w, x.w, acc);
    }
    const float other = __shfl_xor_sync(0xffffffffu, acc, 1);
    if (half == 0)
        hs[j] = fmaxf(acc + other + b1[j], 0.0f) * w2[j];
    __syncthreads();

#pragma unroll
    for (int s2 = 256; s2 > 0; s2 >>= 1) {
        if (t < s2) hs[t] += hs[t + s2];
        __syncthreads();
    }
    if (t == 0) out[0] = hs[0] + b2[0];
}

// ---------------------------------------------------------------------------
// Launch
// ---------------------------------------------------------------------------
extern "C" void kernel_launch(void* const* d_in, const int* in_sizes, int n_in,
                              void* d_out, int out_size)
{
    const float* co = (const float*)d_in[0];
    const float* cm = (const float*)d_in[1];
    const float* p0 = (const float*)d_in[2];
    const float* p1 = (const float*)d_in[3];
    const float* p2 = (const float*)d_in[4];
    const float* p3 = (const float*)d_in[5];
    const float* f0 = (const float*)d_in[6];
    const float* f1 = (const float*)d_in[7];
    const float* f2 = (const float*)d_in[8];
    const float* f3 = (const float*)d_in[9];
    const float* w1 = (const float*)d_in[10];
    const float* b1 = (const float*)d_in[11];
    const float* w2 = (const float*)d_in[12];
    const float* b2 = (const float*)d_in[13];
    float* out = (float*)d_out;

    nn_kernel<<<512, 128>>>(co, cm, p0, p1, p2, p3);
    gather_max_kernel<<<256, 256>>>(f0, f1, f2, f3);
    fc_kernel<<<1, 1024>>>(w1, b1, w2, b2, out);
}

// round 5
// speedup vs baseline: 2.2265x; 2.2265x over previous
#include <cuda_runtime.h>
#include <float.h>

// ---------------------------------------------------------------------------
// Problem shape
// ---------------------------------------------------------------------------
#define M_Q   2048
#define N_P   32768
#define D_F   256
#define D2    512

#define NPART 16
#define PART  (N_P / NPART)      // 2048 candidates per partition (== one tile)
#define TP    (PART / 2)         // 1024 packed units
#define QPW   8                  // queries per warp
#define SUBP  128                // packed units per sub-block (256 candidates)
#define NSUB  (TP / SUBP)        // 8 sub-blocks

typedef unsigned long long ull;

// ---------------------------------------------------------------------------
// Device scratch
// ---------------------------------------------------------------------------
__device__ float2       g_nn_part[4][M_Q][NPART];  // (best d2', sub-base bits)
__device__ unsigned int g_xmax[D2];                // order-encoded channel max
__device__ float        g_h[D2];                   // fc1 out * w2

// ---------------------------------------------------------------------------
// Packed f32x2 helpers
// ---------------------------------------------------------------------------
__device__ __forceinline__ ull fma2(ull a, ull b, ull c) {
    ull d;
    asm("fma.rn.f32x2 %0, %1, %2, %3;" : "=l"(d) : "l"(a), "l"(b), "l"(c));
    return d;
}
__device__ __forceinline__ ull mul2(ull a, ull b) {
    ull d;
    asm("mul.rn.f32x2 %0, %1, %2;" : "=l"(d) : "l"(a), "l"(b));
    return d;
}
__device__ __forceinline__ void fma2u(ull a, ull b, ull c, float& lo, float& hi) {
    asm("{\n\t.reg .b64 t;\n\t"
        "fma.rn.f32x2 t, %2, %3, %4;\n\t"
        "mov.b64 {%0, %1}, t;\n\t}"
        : "=f"(lo), "=f"(hi) : "l"(a), "l"(b), "l"(c));
}
__device__ __forceinline__ ull pack2(float lo, float hi) {
    ull r;
    asm("mov.b64 %0, {%1, %2};" : "=l"(r) : "f"(lo), "f"(hi));
    return r;
}

// Order-preserving float<->uint for atomicMax over mixed-sign floats.
__device__ __forceinline__ unsigned int enc_f(float f) {
    unsigned int u = __float_as_uint(f);
    return (u & 0x80000000u) ? ~u : (u | 0x80000000u);
}
__device__ __forceinline__ float dec_f(unsigned int u) {
    return __uint_as_float((u & 0x80000000u) ? (u & 0x7FFFFFFFu) : ~u);
}

// ---------------------------------------------------------------------------
// Kernel 1: brute-force NN, min-only loop + 256-cand sub-block tracking.
// d2' = |p|^2 - 2 q.p  (argmin-equivalent to |q-p|^2)
// Grid: 2048 blocks = 32 qblocks x 4 searches x 16 partitions. 256 thr.
// ---------------------------------------------------------------------------
__global__ __launch_bounds__(256, 3)
void nn_kernel(const float* __restrict__ co, const float* __restrict__ cm,
               const float* __restrict__ p0, const float* __restrict__ p1,
               const float* __restrict__ p2, const float* __restrict__ p3)
{
    const int bx     = blockIdx.x;
    const int part   = bx & 15;
    const int search = (bx >> 4) & 3;
    const int qblk   = bx >> 6;               // 0..31
    const int tid    = threadIdx.x;
    const int warp   = tid >> 5;
    const int lane   = tid & 31;

    if (bx < 2) g_xmax[bx * 256 + tid] = 0u;  // init for gather stage

    const float* __restrict__ q   = (search < 2) ? co : cm;
    const float* __restrict__ pos = (search == 0) ? p0 :
                                    (search == 1) ? p1 :
                                    (search == 2) ? p2 : p3;

    const int qbase = qblk * 64 + warp * QPW;

    ull   cx2[QPW], cy2[QPW], cz2[QPW];
    float best[QPW];
    int   bsub[QPW];
#pragma unroll
    for (int j = 0; j < QPW; j++) {
        const int qi = qbase + j;
        const float nx = -2.0f * q[qi * 3 + 0];
        const float ny = -2.0f * q[qi * 3 + 1];
        const float nz = -2.0f * q[qi * 3 + 2];
        cx2[j] = pack2(nx, nx);
        cy2[j] = pack2(ny, ny);
        cz2[j] = pack2(nz, nz);
        best[j] = FLT_MAX;
        bsub[j] = 0;
    }

    __shared__ ull sx[TP], sy[TP], sz[TP], sw[TP];   // 32 KB

    const int pbase = part * PART;

    // tile load: pack candidate pairs, precompute |p|^2 (fixed op order)
    for (int u = tid; u < TP; u += 256) {
        const float2* pp = (const float2*)(pos + (size_t)(pbase + 2 * u) * 3);
        const float2 a = pp[0];            // x0 y0
        const float2 b = pp[1];            // z0 x1
        const float2 c = pp[2];            // y1 z1
        const ull x2 = pack2(a.x, b.y);
        const ull y2 = pack2(a.y, c.x);
        const ull z2 = pack2(b.x, c.y);
        ull w2 = mul2(z2, z2);
        w2 = fma2(y2, y2, w2);
        w2 = fma2(x2, x2, w2);
        sx[u] = x2; sy[u] = y2; sz[u] = z2; sw[u] = w2;
    }
    __syncthreads();

#pragma unroll 1
    for (int s = 0; s < NSUB; s++) {
        float tmin[QPW];
#pragma unroll
        for (int j = 0; j < QPW; j++) tmin[j] = best[j];

#pragma unroll
        for (int kk = 0; kk < SUBP / 32; kk++) {       // 4 k-iters
            const int k = s * SUBP + kk * 32 + lane;
            const ull x2 = sx[k];
            const ull y2 = sy[k];
            const ull z2 = sz[k];
            const ull w2 = sw[k];
#pragma unroll
            for (int j = 0; j < QPW; j++) {
                ull t2 = fma2(x2, cx2[j], w2);
                t2 = fma2(y2, cy2[j], t2);
                float lo, hi;
                fma2u(z2, cz2[j], t2, lo, hi);
                tmin[j] = fminf(tmin[j], fminf(lo, hi));
            }
        }

        const int gb = pbase + s * (2 * SUBP);         // candidate base
#pragma unroll
        for (int j = 0; j < QPW; j++) {
            if (tmin[j] < best[j]) { best[j] = tmin[j]; bsub[j] = gb; }
        }
    }

    // cross-lane lexicographic (best, bsub) reduce
#pragma unroll
    for (int off = 16; off; off >>= 1) {
#pragma unroll
        for (int j = 0; j < QPW; j++) {
            const float ob = __shfl_xor_sync(0xffffffffu, best[j], off);
            const int   og = __shfl_xor_sync(0xffffffffu, bsub[j], off);
            if (ob < best[j] || (ob == best[j] && og < bsub[j])) {
                best[j] = ob; bsub[j] = og;
            }
        }
    }
    if (lane == 0) {
#pragma unroll
        for (int j = 0; j < QPW; j++)
            g_nn_part[search][qbase + j][part] =
                make_float2(best[j], __int_as_float(bsub[j]));
    }
}

// ---------------------------------------------------------------------------
// Kernel 2: resolve partitions + rescan 256-cand sub-block for exact index,
// then gather feat rows, avg left/right, max-pool (atomicMax, deterministic).
// Grid: 256 blocks = 2 sides x 128 chunks (16 rows). 256 thr.
// ---------------------------------------------------------------------------
__global__ __launch_bounds__(256)
void gather_kernel(const float* __restrict__ co, const float* __restrict__ cm,
                   const float* __restrict__ p0, const float* __restrict__ p1,
                   const float* __restrict__ p2, const float* __restrict__ p3,
                   const float* __restrict__ f0, const float* __restrict__ f1,
                   const float* __restrict__ f2, const float* __restrict__ f3)
{
    const int side  = blockIdx.x >> 7;     // 0 = orig, 1 = mut
    const int chunk = blockIdx.x & 127;
    const int m0    = chunk * 16;
    const int tid   = threadIdx.x;
    const int warp  = tid >> 5;
    const int lane  = tid & 31;

    __shared__ int sj[2][16];

    // 8 warps x 4 (which,row) pairs = 32 resolves+rescans, each done once.
    for (int pr = warp * 4; pr < warp * 4 + 4; pr++) {
        const int which = pr >> 4;                     // 0 = left, 1 = right
        const int ml    = pr & 15;
        const int m     = m0 + ml;
        const int s     = side * 2 + which;

        // resolve across 16 partitions: lex-min (d2, sub-base)
        float v;
        int   g;
        if (lane < NPART) {
            const float2 p = g_nn_part[s][m][lane];
            v = p.x; g = __float_as_int(p.y);
        } else {
            v = FLT_MAX; g = 0x7fffffff;
        }
#pragma unroll
        for (int off = 16; off; off >>= 1) {
            const float ov = __shfl_xor_sync(0xffffffffu, v, off);
            const int   og = __shfl_xor_sync(0xffffffffu, g, off);
            if (ov < v || (ov == v && og < g)) { v = ov; g = og; }
        }
        const float wbest = v;      // warp-uniform
        const int   gb    = g;      // winning 256-cand sub-block base (even)

        // query constants (identical math to nn_kernel)
        const float* __restrict__ qb = (s < 2) ? co : cm;
        const float nx = -2.0f * qb[m * 3 + 0];
        const float ny = -2.0f * qb[m * 3 + 1];
        const float nz = -2.0f * qb[m * 3 + 2];
        const ull cx2 = pack2(nx, nx);
        const ull cy2 = pack2(ny, ny);
        const ull cz2 = pack2(nz, nz);

        const float* __restrict__ pos = (s == 0) ? p0 : (s == 1) ? p1 :
                                        (s == 2) ? p2 : p3;

        int midx = 0x7fffffff;
#pragma unroll
        for (int kk = 0; kk < SUBP / 32; kk++) {       // 4 k-iters
            const int i0 = gb + 2 * (kk * 32 + lane);
            const float2* pp = (const float2*)(pos + (size_t)i0 * 3);
            const float2 a = pp[0];
            const float2 b = pp[1];
            const float2 c = pp[2];
            const ull x2 = pack2(a.x, b.y);
            const ull y2 = pack2(a.y, c.x);
            const ull z2 = pack2(b.x, c.y);
            ull w2 = mul2(z2, z2);
            w2 = fma2(y2, y2, w2);
            w2 = fma2(x2, x2, w2);
            ull t2 = fma2(x2, cx2, w2);
            t2 = fma2(y2, cy2, t2);
            float lo, hi;
            fma2u(z2, cz2, t2, lo, hi);
            if (lo == wbest) midx = min(midx, i0);
            if (hi == wbest) midx = min(midx, i0 + 1);
        }
#pragma unroll
        for (int off = 16; off; off >>= 1)
            midx = min(midx, __shfl_xor_sync(0xffffffffu, midx, off));

        if (lane == 0) sj[which][ml] = midx;
    }
    __syncthreads();

    const float* __restrict__ fa = side ? f2 : f0;
    const float* __restrict__ fb = side ? f3 : f1;
    const int c = tid;

    float mx = -FLT_MAX;
#pragma unroll
    for (int m = 0; m < 16; m++) {
        const float val = 0.5f * (fa[(size_t)sj[0][m] * D_F + c] +
                                  fb[(size_t)sj[1][m] * D_F + c]);
        mx = fmaxf(mx, val);
    }
    atomicMax(&g_xmax[side * 256 + c], enc_f(mx));
}

// ---------------------------------------------------------------------------
// Kernel 3: fc1 spread over 128 blocks (4 rows each, warp per row).
// Writes g_h[j] = relu(w1[j,:].x + b1[j]) * w2[j].
// ---------------------------------------------------------------------------
__global__ __launch_bounds__(128)
void fc1_kernel(const float* __restrict__ w1, const float* __restrict__ b1,
                const float* __restrict__ w2)
{
    __shared__ float xs[D2];
    const int tid  = threadIdx.x;
    const int warp = tid >> 5;
    const int lane = tid & 31;

    for (int i = tid; i < D2; i += 128) xs[i] = dec_f(g_xmax[i]);
    __syncthreads();

    const int j = blockIdx.x * 4 + warp;
    const float4* __restrict__ wr4 = (const float4*)(w1 + (size_t)j * D2);
    const float4* __restrict__ xs4 = (const float4*)xs;

    float acc = 0.0f;
#pragma unroll
    for (int k = lane; k < D2 / 4; k += 32) {          // 4 float4 per lane
        const float4 w = wr4[k];
        const float4 x = xs4[k];
        acc = fmaf(w.x, x.x, acc);
        acc = fmaf(w.y, x.y, acc);
        acc = fmaf(w.z, x.z, acc);
        acc = fmaf(w.w, x.w, acc);
    }
#pragma unroll
    for (int off = 16; off; off >>= 1)
        acc += __shfl_down_sync(0xffffffffu, acc, off);

    if (lane == 0)
        g_h[j] = fmaxf(acc + b1[j], 0.0f) * w2[j];
}

// ---------------------------------------------------------------------------
// Kernel 4: fc2 scalar sum.
// ---------------------------------------------------------------------------
__global__ __launch_bounds__(128)
void fc2_kernel(const float* __restrict__ b2, float* __restrict__ out)
{
    __shared__ float red[4];
    const int tid  = threadIdx.x;
    const int warp = tid >> 5;
    const int lane = tid & 31;

    const float4 v = ((const float4*)g_h)[tid];        // 128 float4 = 512
    float acc = v.x + v.y + v.z + v.w;
#pragma unroll
    for (int off = 16; off; off >>= 1)
        acc += __shfl_down_sync(0xffffffffu, acc, off);
    if (lane == 0) red[warp] = acc;
    __syncthreads();
    if (tid == 0)
        out[0] = red[0] + red[1] + red[2] + red[3] + b2[0];
}

// ---------------------------------------------------------------------------
// Launch
// ---------------------------------------------------------------------------
extern "C" void kernel_launch(void* const* d_in, const int* in_sizes, int n_in,
                              void* d_out, int out_size)
{
    const float* co = (const float*)d_in[0];
    const float* cm = (const float*)d_in[1];
    const float* p0 = (const float*)d_in[2];
    const float* p1 = (const float*)d_in[3];
    const float* p2 = (const float*)d_in[4];
    const float* p3 = (const float*)d_in[5];
    const float* f0 = (const float*)d_in[6];
    const float* f1 = (const float*)d_in[7];
    const float* f2 = (const float*)d_in[8];
    const float* f3 = (const float*)d_in[9];
    const float* w1 = (const float*)d_in[10];
    const float* b1 = (const float*)d_in[11];
    const float* w2 = (const float*)d_in[12];
    const float* b2 = (const float*)d_in[13];
    float* out = (float*)d_out;

    nn_kernel<<<2048, 256>>>(co, cm, p0, p1, p2, p3);
    gather_kernel<<<256, 256>>>(co, cm, p0, p1, p2, p3, f0, f1, f2, f3);
    fc1_kernel<<<128, 128>>>(w1, b1, w2);
    fc2_kernel<<<1, 128>>>(b2, out);
}